// round 3
// baseline (speedup 1.0000x reference)
#include <cuda_runtime.h>
#include <cstdint>
#include <cstddef>

// ScalarWaveletRecombiner: out[n,o] = W2[o]·silu(W1[o]·x[n] + b1[o]) + b2[o]
// x:[NC,64] W1:[32,128,64] b1:[32,128] W2:[32,128] b2:[32] -> out:[NC,32]
//
// Fused tf32 mma.sync kernel:
//   grid = (NC/256, 16); block = 512 threads (16 warps, 16 rows each, 2 MLPs/block)
//   GEMM1 via mma.m16n8k8.tf32 (RNA-converted operands, fp32 accum),
//   epilogue (bias + silu + W2 reduction) fused in registers + shfl.

#define KDIM 64
#define HDIM 128
#define ODIM 32
#define OPB 2
#define ROWS_PER_BLOCK 256
#define THREADS 512

// smem layout (bytes)
#define WS_OFF   0                      // tf32 W1, B-fragment order: [2][8][8][128] u32 = 65536
#define XS_OFF   65536                  // x tile [256][68] f32 = 69632
#define B1_OFF   135168                 // [2][128] f32
#define W2_OFF   136192                 // [2][128] f32
#define B2_OFF   137216                 // [2] f32
#define SMEM_BYTES 137232

__device__ __forceinline__ unsigned f2tf32(float f) {
    unsigned r;
    asm("cvt.rna.tf32.f32 %0, %1;" : "=r"(r) : "f"(f));
    return r;
}

__device__ __forceinline__ void mma_tf32(float* c, const unsigned* a, unsigned b0, unsigned b1) {
    asm volatile(
        "mma.sync.aligned.m16n8k8.row.col.f32.tf32.tf32.f32 "
        "{%0,%1,%2,%3},{%4,%5,%6,%7},{%8,%9},{%0,%1,%2,%3};"
        : "+f"(c[0]), "+f"(c[1]), "+f"(c[2]), "+f"(c[3])
        : "r"(a[0]), "r"(a[1]), "r"(a[2]), "r"(a[3]), "r"(b0), "r"(b1));
}

__device__ __forceinline__ float silu_f(float v) {
    return v * (1.0f / (1.0f + __expf(-v)));
}

__global__ __launch_bounds__(THREADS, 1)
void swr_kernel(const float* __restrict__ x, const float* __restrict__ W1,
                const float* __restrict__ b1, const float* __restrict__ W2,
                const float* __restrict__ b2, float* __restrict__ out, int NC)
{
    extern __shared__ char smem[];
    unsigned* ws = (unsigned*)(smem + WS_OFF);
    float*    xs = (float*)(smem + XS_OFF);
    float*   b1s = (float*)(smem + B1_OFF);
    float*   w2s = (float*)(smem + W2_OFF);
    float*   b2s = (float*)(smem + B2_OFF);

    const int tid = threadIdx.x;
    const int R0  = blockIdx.x * ROWS_PER_BLOCK;
    const int o0  = blockIdx.y * OPB;

    // ---- stage x tile: [256][64] -> xs row stride 68 (conflict-free A loads) ----
    for (int idx = tid; idx < ROWS_PER_BLOCK * (KDIM / 4); idx += THREADS) {
        int r  = idx >> 4;
        int c4 = (idx & 15) << 2;
        float4 v = *(const float4*)(x + (size_t)(R0 + r) * KDIM + c4);
        *(float4*)(xs + r * 68 + c4) = v;
    }

    // ---- stage W1 pre-swizzled into mma B-fragment order, tf32 ----
    // ws[((ol*8+kk)*8+np)*128 + lane*4 + j]:
    //   j0 = b0(n=2np), j1 = b1(n=2np), j2 = b0(n=2np+1), j3 = b1(n=2np+1)
    //   b0: B[k=kk*8+tig][n] ; b1: B[k=kk*8+tig+4][n] ; B[k][n] = W1[o][h=n*8+gid][k]
    for (int idx = tid; idx < OPB * 8 * 8 * 128; idx += THREADS) {
        int j  = idx & 3;
        int ln = (idx >> 2) & 31;
        int np = (idx >> 7) & 7;
        int kk = (idx >> 10) & 7;
        int ol = idx >> 13;
        int gid = ln >> 2, tg = ln & 3;
        int n = 2 * np + (j >> 1);
        int h = n * 8 + gid;
        int k = kk * 8 + tg + ((j & 1) << 2);
        ws[idx] = f2tf32(W1[((size_t)(o0 + ol) * HDIM + h) * KDIM + k]);
    }

    if (tid < OPB * HDIM) {
        int ol = tid >> 7, h = tid & 127;
        b1s[tid] = b1[(o0 + ol) * HDIM + h];
        w2s[tid] = W2[(o0 + ol) * HDIM + h];
    }
    if (tid < OPB) b2s[tid] = b2[o0 + tid];
    __syncthreads();

    const int w    = tid >> 5;
    const int lane = tid & 31;
    const int gID  = lane >> 2;
    const int tig  = lane & 3;
    const int rbase = w * 16;

    // ---- A fragments for all 8 k-steps (rows rbase+gID, rbase+gID+8) ----
    unsigned a[8][4];
    #pragma unroll
    for (int kk = 0; kk < 8; kk++) {
        int c0 = kk * 8 + tig;
        a[kk][0] = f2tf32(xs[(rbase + gID) * 68 + c0]);
        a[kk][1] = f2tf32(xs[(rbase + gID + 8) * 68 + c0]);
        a[kk][2] = f2tf32(xs[(rbase + gID) * 68 + c0 + 4]);
        a[kk][3] = f2tf32(xs[(rbase + gID + 8) * 68 + c0 + 4]);
    }

    #pragma unroll
    for (int ol = 0; ol < OPB; ol++) {
        float c[16][4];
        #pragma unroll
        for (int n = 0; n < 16; n++) {
            c[n][0] = 0.f; c[n][1] = 0.f; c[n][2] = 0.f; c[n][3] = 0.f;
        }

        #pragma unroll
        for (int kk = 0; kk < 8; kk++) {
            const uint4* wrow = (const uint4*)(ws + ((ol * 8 + kk) * 8) * 128);
            #pragma unroll
            for (int np = 0; np < 8; np++) {
                uint4 b = wrow[np * 32 + lane];
                mma_tf32(c[2 * np],     a[kk], b.x, b.y);
                mma_tf32(c[2 * np + 1], a[kk], b.z, b.w);
            }
        }

        // ---- fused epilogue: bias + silu + W2-weighted reduce over H ----
        float s0 = 0.f, s1 = 0.f;
        #pragma unroll
        for (int n = 0; n < 16; n++) {
            #pragma unroll
            for (int jj = 0; jj < 2; jj++) {
                int col = n * 8 + tig * 2 + jj;
                float bb = b1s[ol * 128 + col];
                float ww = w2s[ol * 128 + col];
                s0 += silu_f(c[n][jj]     + bb) * ww;
                s1 += silu_f(c[n][2 + jj] + bb) * ww;
            }
        }
        // reduce across the 4 threads sharing a row (tig = low 2 lane bits)
        s0 += __shfl_xor_sync(0xffffffffu, s0, 1);
        s0 += __shfl_xor_sync(0xffffffffu, s0, 2);
        s1 += __shfl_xor_sync(0xffffffffu, s1, 1);
        s1 += __shfl_xor_sync(0xffffffffu, s1, 2);

        if (tig == 0) {
            int row = R0 + rbase + gID;
            float bo = b2s[ol];
            out[(size_t)row * ODIM + (o0 + ol)]       = s0 + bo;
            out[(size_t)(row + 8) * ODIM + (o0 + ol)] = s1 + bo;
        }
    }
}

extern "C" void kernel_launch(void* const* d_in, const int* in_sizes, int n_in,
                              void* d_out, int out_size)
{
    const float* x  = (const float*)d_in[0];  // [NC, 64]
    const float* W1 = (const float*)d_in[1];  // [32, 128, 64]
    const float* b1 = (const float*)d_in[2];  // [32, 128]
    const float* W2 = (const float*)d_in[3];  // [32, 128]
    const float* b2 = (const float*)d_in[4];  // [32]
    float* out = (float*)d_out;               // [NC, 32]

    int NC = in_sizes[0] / KDIM;              // 131072

    cudaFuncSetAttribute(swr_kernel, cudaFuncAttributeMaxDynamicSharedMemorySize, SMEM_BYTES);

    dim3 grid(NC / ROWS_PER_BLOCK, ODIM / OPB);
    swr_kernel<<<grid, THREADS, SMEM_BYTES>>>(x, W1, b1, W2, b2, out, NC);
}